// round 3
// baseline (speedup 1.0000x reference)
#include <cuda_runtime.h>

#define NN 50000
#define EE 500000
#define HH 128
// per-node feature block = 4 channels * 128 = 512 floats

// ---- scratch (static __device__ arrays; no runtime allocation) ----
__device__ int   g_cnt[NN];
__device__ int   g_off[NN + 1];
__device__ int   g_cur[NN];
__device__ int   g_cols[EE];
__device__ int   g_is32;                    // 1 if edge_index buffer is int32
__device__ float g_agg[(size_t)NN * 512];   // aggregated raw features, layout == x

// ---------------- dtype detection ----------------
__global__ void k_dtype_init() { if (threadIdx.x == 0) g_is32 = 0; }

// Interpret first EE elements as int64. That spans exactly 2*EE int32 words
// (the whole buffer if it is int32), so the read is in-bounds either way.
// Any out-of-range value => buffer is int32.
__global__ void k_dtype_detect(const long long* __restrict__ ei) {
    int e = blockIdx.x * blockDim.x + threadIdx.x;
    if (e < EE) {
        long long v = ei[e];
        if (v < 0 || v >= NN) atomicOr(&g_is32, 1);
    }
}

__device__ __forceinline__ int load_idx(const void* ei, int pos, int is32) {
    long long v;
    if (is32) v = ((const int*)ei)[pos];
    else      v = ((const long long*)ei)[pos];
    int r = (int)v;
    // defensive clamp: never fault, fail via rel_err instead
    if (r < 0) r = 0;
    if (r >= NN) r = NN - 1;
    return r;
}

// ---------------- CSR build ----------------
__global__ void k_zero_cnt() {
    int i = blockIdx.x * blockDim.x + threadIdx.x;
    if (i < NN) g_cnt[i] = 0;
}

__global__ void k_hist(const void* __restrict__ ei) {
    int e = blockIdx.x * blockDim.x + threadIdx.x;
    if (e < EE) {
        int is32 = g_is32;
        int r = load_idx(ei, e, is32);           // row = edge_index[0][e]
        atomicAdd(&g_cnt[r], 1);
    }
}

// single-block exclusive scan of NN counts
__global__ void k_scan() {
    __shared__ int part[1024];
    int t = threadIdx.x;
    const int CH = (NN + 1023) / 1024;     // 49
    int beg = t * CH;
    int end = beg + CH; if (end > NN) end = NN;
    int s = 0;
    for (int i = beg; i < end; i++) s += g_cnt[i];
    part[t] = s;
    __syncthreads();
    for (int d = 1; d < 1024; d <<= 1) {
        int v = (t >= d) ? part[t - d] : 0;
        __syncthreads();
        part[t] += v;
        __syncthreads();
    }
    int run = (t == 0) ? 0 : part[t - 1];
    for (int i = beg; i < end; i++) {
        int c = g_cnt[i];
        g_off[i] = run;
        g_cur[i] = run;
        run += c;
    }
    if (t == 1023) g_off[NN] = EE;
}

__global__ void k_fill(const void* __restrict__ ei) {
    int e = blockIdx.x * blockDim.x + threadIdx.x;
    if (e < EE) {
        int is32 = g_is32;
        int r = load_idx(ei, e, is32);           // row
        int c = load_idx(ei, EE + e, is32);      // col
        int p = atomicAdd(&g_cur[r], 1);
        g_cols[p] = c;
    }
}

// ---------------- aggregate raw features: agg[n] = sum_{e: row=n} x[col_e] ----------------
// one block (128 threads) per node; thread t owns float4 #t of the 512-float feature
__global__ void __launch_bounds__(128) k_agg(const float4* __restrict__ xv) {
    int n = blockIdx.x;
    int t = threadIdx.x;
    int beg = g_off[n], end = g_off[n + 1];
    float4 acc = make_float4(0.f, 0.f, 0.f, 0.f);
    int j = beg;
    for (; j + 1 < end; j += 2) {
        int c0 = g_cols[j];
        int c1 = g_cols[j + 1];
        float4 v0 = xv[(size_t)c0 * 128 + t];
        float4 v1 = xv[(size_t)c1 * 128 + t];
        acc.x += v0.x; acc.y += v0.y; acc.z += v0.z; acc.w += v0.w;
        acc.x += v1.x; acc.y += v1.y; acc.z += v1.z; acc.w += v1.w;
    }
    if (j < end) {
        int c0 = g_cols[j];
        float4 v0 = xv[(size_t)c0 * 128 + t];
        acc.x += v0.x; acc.y += v0.y; acc.z += v0.z; acc.w += v0.w;
    }
    ((float4*)g_agg)[(size_t)n * 128 + t] = acc;
}

// ---------------- fused GEMM: out_row = [x_row | agg_row] @ [Wroot | Wrel].T (+bias) ----------------
// MODE 0: scalar rows, m -> node m, channel 0, offset m*512
// MODE 1: vector rows, m -> node m/3, channel 1+m%3
// Block tile: 128 rows x 128 outputs, K = 256 in chunks of 8. 256 threads, 8x8 micro-tile.
template <int MODE, bool BIAS>
__global__ void __launch_bounds__(256) k_gemm(const float* __restrict__ X,
                                              const float* __restrict__ Wroot,
                                              const float* __restrict__ Wrel,
                                              const float* __restrict__ bias,
                                              float* __restrict__ out, int M) {
    __shared__ float As[8][128];
    __shared__ float Bs[8][128];
    __shared__ int   roff[128];

    int tid = threadIdx.x;
    int mbase = blockIdx.x * 128;

    if (tid < 128) {
        int m = mbase + tid;
        if (m >= M) m = M - 1;          // clamp: duplicate loads, stores guarded later
        int off;
        if (MODE == 0) {
            off = m * 512;
        } else {
            int n = m / 3;
            int c = 1 + (m % 3);
            off = n * 512 + c * 128;
        }
        roff[tid] = off;
    }
    __syncthreads();

    float acc[8][8];
#pragma unroll
    for (int i = 0; i < 8; i++)
#pragma unroll
        for (int j = 0; j < 8; j++) acc[i][j] = 0.f;

    int lr  = tid >> 1;          // 0..127 : row index (A) / output index (B)
    int lkq = (tid & 1) * 4;     // 0 or 4 : which float4 of the 8-wide k-chunk

    int tm = tid >> 4;           // 0..15 -> rows tm*8..tm*8+7
    int tn = tid & 15;           // 0..15 -> cols tn*8..tn*8+7

    const float* Agg = g_agg;

#pragma unroll 1
    for (int kc = 0; kc < 32; kc++) {
        int k0 = kc * 8;
        bool first_half = (k0 < 128);
        int  kk = first_half ? k0 : (k0 - 128);
        const float* srcA = first_half ? X : Agg;
        const float* srcB = first_half ? Wroot : Wrel;

        float4 av = *(const float4*)(srcA + roff[lr] + kk + lkq);
        float4 bv = *(const float4*)(srcB + lr * 128 + kk + lkq);

        __syncthreads();   // previous chunk's compute done before overwrite
        As[lkq + 0][lr] = av.x;
        As[lkq + 1][lr] = av.y;
        As[lkq + 2][lr] = av.z;
        As[lkq + 3][lr] = av.w;
        Bs[lkq + 0][lr] = bv.x;
        Bs[lkq + 1][lr] = bv.y;
        Bs[lkq + 2][lr] = bv.z;
        Bs[lkq + 3][lr] = bv.w;
        __syncthreads();

#pragma unroll
        for (int p = 0; p < 8; p++) {
            float a[8], b[8];
            *(float4*)&a[0] = *(const float4*)&As[p][tm * 8];
            *(float4*)&a[4] = *(const float4*)&As[p][tm * 8 + 4];
            *(float4*)&b[0] = *(const float4*)&Bs[p][tn * 8];
            *(float4*)&b[4] = *(const float4*)&Bs[p][tn * 8 + 4];
#pragma unroll
            for (int i = 0; i < 8; i++)
#pragma unroll
                for (int j = 0; j < 8; j++)
                    acc[i][j] += a[i] * b[j];
        }
    }

    // epilogue
    float bs[8];
#pragma unroll
    for (int j = 0; j < 8; j++) bs[j] = BIAS ? bias[tn * 8 + j] : 0.f;

#pragma unroll
    for (int i = 0; i < 8; i++) {
        int lm = tm * 8 + i;
        int m  = mbase + lm;
        if (m < M) {
            float* o = out + roff[lm] + tn * 8;
            float4 v0, v1;
            v0.x = acc[i][0] + bs[0]; v0.y = acc[i][1] + bs[1];
            v0.z = acc[i][2] + bs[2]; v0.w = acc[i][3] + bs[3];
            v1.x = acc[i][4] + bs[4]; v1.y = acc[i][5] + bs[5];
            v1.z = acc[i][6] + bs[6]; v1.w = acc[i][7] + bs[7];
            *(float4*)(o)     = v0;
            *(float4*)(o + 4) = v1;
        }
    }
}

extern "C" void kernel_launch(void* const* d_in, const int* in_sizes, int n_in,
                              void* d_out, int out_size) {
    const float* x        = (const float*)d_in[0];
    const void*  ei       = d_in[1];
    const float* W_s_rel  = (const float*)d_in[2];
    const float* W_s_root = (const float*)d_in[3];
    const float* b_s_root = (const float*)d_in[4];
    const float* W_v_rel  = (const float*)d_in[5];
    const float* W_v_root = (const float*)d_in[6];
    float*       out      = (float*)d_out;

    k_dtype_init<<<1, 32>>>();
    k_dtype_detect<<<(EE + 255) / 256, 256>>>((const long long*)ei);

    k_zero_cnt<<<(NN + 255) / 256, 256>>>();
    k_hist<<<(EE + 255) / 256, 256>>>(ei);
    k_scan<<<1, 1024>>>();
    k_fill<<<(EE + 255) / 256, 256>>>(ei);
    k_agg<<<NN, 128>>>((const float4*)x);

    // scalar channel: out[:,0,:] = x_s @ Ws_root.T + b + agg_s @ Ws_rel.T
    k_gemm<0, true><<<(NN + 127) / 128, 256>>>(x, W_s_root, W_s_rel, b_s_root, out, NN);
    // vector channels: out[:,1:,:] = x_v @ Wv_root.T + agg_v @ Wv_rel.T
    k_gemm<1, false><<<(3 * NN + 127) / 128, 256>>>(x, W_v_root, W_v_rel, nullptr, out, 3 * NN);
}